// round 15
// baseline (speedup 1.0000x reference)
#include <cuda_runtime.h>

#define H 2048
#define S 2048
#define V 50257
#define CHUNKS 32
#define NPART 64

// ---- scratch ----
__device__ float g_attn_partial[CHUNKS * H];
__device__ float g_attn_applied[H];
__device__ float g_p1[H];         // comb partial: embedded half
__device__ float g_p2[H];         // comb partial: attn half
__device__ float g_gx[3 * H];
__device__ float g_gh[3 * H];
__device__ float g_hnew[H];
__device__ float g_logits[V];
__device__ float g_sumpart[NPART];

__device__ __forceinline__ float warp_sum(float v) {
#pragma unroll
    for (int o = 16; o > 0; o >>= 1) v += __shfl_down_sync(0xffffffffu, v, o);
    return v;
}

// ---- A (stream 3): partial column sums of encoder_outputs ----
__global__ void colsum_partial(const float* __restrict__ enc) {
    int col = blockIdx.x * 256 + threadIdx.x;          // 8 col-blocks
    int s0 = blockIdx.y * (S / CHUNKS);                // 32 row-chunks of 64
    float acc = 0.f;
#pragma unroll 8
    for (int s = 0; s < S / CHUNKS; ++s)
        acc += __ldg(&enc[(size_t)(s0 + s) * H + col]);
    g_attn_partial[blockIdx.y * H + col] = acc;
}

// ---- R (stream 3): reduce partials -> attn_applied; emit attn_weights = 1.0 ----
__global__ void colsum_reduce(float* __restrict__ out_attn) {
    int h = blockIdx.x * 64 + threadIdx.x;             // 32 blocks x 64 threads
    float acc = 0.f;
#pragma unroll
    for (int c = 0; c < CHUNKS; ++c) acc += g_attn_partial[c * H + h];
    g_attn_applied[h] = acc;
    out_attn[h] = 1.0f;   // out_attn only 4B-aligned: scalar store required
}

// ---- B1 (main, t=0, no deps): embedded half of comb -> g_p1. 256 blocks ----
__global__ void comb_emb(const float* __restrict__ comb_w,
                         const float* __restrict__ emb,
                         const int* __restrict__ tok) {
    int warp = threadIdx.x >> 5, lane = threadIdx.x & 31;
    int h = blockIdx.x * 8 + warp;                     // 0..2047
    const float4* w4 = (const float4*)(comb_w + (size_t)h * (2 * H));
    const float4* v4 = (const float4*)(emb + (size_t)tok[0] * H);
    float acc = 0.f;
#pragma unroll
    for (int i = 0; i < 16; ++i) {
        float4 wv = __ldcs(&w4[i * 32 + lane]);
        float4 xv = __ldg(&v4[i * 32 + lane]);
        acc += wv.x * xv.x + wv.y * xv.y + wv.z * xv.z + wv.w * xv.w;
    }
    acc = warp_sum(acc);
    if (lane == 0) g_p1[h] = acc;
}

// ---- B2 (main, after colsum): attn half of comb -> g_p2. 256 blocks ----
__global__ void comb_attn(const float* __restrict__ comb_w) {
    int warp = threadIdx.x >> 5, lane = threadIdx.x & 31;
    int h = blockIdx.x * 8 + warp;                     // 0..2047
    const float4* w4 = (const float4*)(comb_w + (size_t)h * (2 * H) + H);
    const float4* v4 = (const float4*)g_attn_applied;
    float acc = 0.f;
#pragma unroll
    for (int i = 0; i < 16; ++i) {
        float4 wv = __ldcs(&w4[i * 32 + lane]);
        float4 xv = v4[i * 32 + lane];
        acc += wv.x * xv.x + wv.y * xv.y + wv.z * xv.z + wv.w * xv.w;
    }
    acc = warp_sum(acc);
    if (lane == 0) g_p2[h] = acc;
}

// ---- C1: hh-gate GEMV (stream 2). 384 blocks x 16 warps, 1 row/warp ----
__global__ void __launch_bounds__(512)
gates_hh(const float* __restrict__ w_hh, const float* __restrict__ b_hh,
         const float* __restrict__ h0) {
    __shared__ float4 vs[H / 4];
    int tid = threadIdx.x;
    const float4* src = (const float4*)h0;
    for (int i = tid; i < H / 4; i += 512) vs[i] = __ldg(&src[i]);
    __syncthreads();
    int warp = tid >> 5, lane = tid & 31;
    int r = blockIdx.x * 16 + warp;                    // 0..6143
    const float4* w4 = (const float4*)(w_hh + (size_t)r * H);
    float acc = 0.f;
#pragma unroll
    for (int i = 0; i < 16; ++i) {
        float4 wv = __ldcs(&w4[i * 32 + lane]);
        float4 xv = vs[i * 32 + lane];
        acc += wv.x * xv.x + wv.y * xv.y + wv.z * xv.z + wv.w * xv.w;
    }
    acc = warp_sum(acc);
    if (lane == 0) g_gh[r] = acc + b_hh[r];
}

// ---- C2: ih-gate GEMV (main). 384 blocks x 16 warps. Staging prologue fuses
//      the comb combine: x = relu(p1 + p2 + comb_b). ----
__global__ void __launch_bounds__(512)
gates_ih(const float* __restrict__ w_ih, const float* __restrict__ b_ih,
         const float* __restrict__ comb_b) {
    __shared__ float4 vs[H / 4];
    int tid = threadIdx.x;
    const float4* p1 = (const float4*)g_p1;
    const float4* p2 = (const float4*)g_p2;
    const float4* cb = (const float4*)comb_b;
    for (int i = tid; i < H / 4; i += 512) {
        float4 a = p1[i], b = p2[i], c = __ldg(&cb[i]);
        float4 x;
        x.x = fmaxf(a.x + b.x + c.x, 0.f);
        x.y = fmaxf(a.y + b.y + c.y, 0.f);
        x.z = fmaxf(a.z + b.z + c.z, 0.f);
        x.w = fmaxf(a.w + b.w + c.w, 0.f);
        vs[i] = x;
    }
    __syncthreads();
    int warp = tid >> 5, lane = tid & 31;
    int r = blockIdx.x * 16 + warp;                    // 0..6143
    const float4* w4 = (const float4*)(w_ih + (size_t)r * H);
    float acc = 0.f;
#pragma unroll
    for (int i = 0; i < 16; ++i) {
        float4 wv = __ldcs(&w4[i * 32 + lane]);
        float4 xv = vs[i * 32 + lane];
        acc += wv.x * xv.x + wv.y * xv.y + wv.z * xv.z + wv.w * xv.w;
    }
    acc = warp_sum(acc);
    if (lane == 0) g_gx[r] = acc + b_ih[r];
}

// ---- D: GRU nonlinearity -> h_new. 32 blocks x 64 threads ----
__global__ void gru_combine(const float* __restrict__ h0, float* __restrict__ out_h) {
    int h = blockIdx.x * 64 + threadIdx.x;
    float r = 1.f / (1.f + expf(-(g_gx[h] + g_gh[h])));
    float z = 1.f / (1.f + expf(-(g_gx[H + h] + g_gh[H + h])));
    float n = tanhf(g_gx[2 * H + h] + r * g_gh[2 * H + h]);
    float hn = (1.f - z) * n + z * h0[h];
    g_hnew[h] = hn;
    out_h[h] = hn;   // scalar store: out + V not 16B-aligned
}

// ---- E: big GEMV — 512-thread blocks (16 warps, 1 row/warp), no epilogue ----
__global__ void __launch_bounds__(512)
out_gemv(const float* __restrict__ out_w, const float* __restrict__ out_b) {
    __shared__ float4 hs[H / 4];
    for (int i = threadIdx.x; i < H / 4; i += 512)
        hs[i] = ((const float4*)g_hnew)[i];
    __syncthreads();
    int warp = threadIdx.x >> 5, lane = threadIdx.x & 31;
    int v = blockIdx.x * 16 + warp;
    if (v >= V) return;
    const float4* w4 = (const float4*)(out_w + (size_t)v * H);
    float acc = 0.f;
#pragma unroll
    for (int i = 0; i < 16; ++i) {
        float4 wv = __ldcs(&w4[i * 32 + lane]);
        float4 xv = hs[i * 32 + lane];
        acc += wv.x * xv.x + wv.y * xv.y + wv.z * xv.z + wv.w * xv.w;
    }
    acc = warp_sum(acc);
    if (lane == 0) g_logits[v] = acc + out_b[v];
}

// ---- F1: partial sum of exp(logits). Logits are O(1): exp safe without max ----
__global__ void sumexp_partial() {
    __shared__ float red[8];
    int t = threadIdx.x;
    float s = 0.f;
    for (int i = blockIdx.x * 256 + t; i < V; i += NPART * 256)
        s += __expf(g_logits[i]);
    s = warp_sum(s);
    if ((t & 31) == 0) red[t >> 5] = s;
    __syncthreads();
    if (t == 0) {
        float ss = 0.f;
#pragma unroll
        for (int j = 0; j < 8; ++j) ss += red[j];
        g_sumpart[blockIdx.x] = ss;
    }
}

// ---- F2: fold partials (deterministic fixed order) and write log_probs ----
__global__ void write_logprobs(float* __restrict__ out) {
    float s = 0.f;
#pragma unroll
    for (int j = 0; j < NPART; ++j) s += g_sumpart[j];
    float lse = logf(s);
    int v = blockIdx.x * 256 + threadIdx.x;
    if (v < V) out[v] = g_logits[v] - lse;
}

// ---- infra: two side streams + events (created once; no device memory) ----
static cudaStream_t make_stream() {
    cudaStream_t t;
    cudaStreamCreateWithFlags(&t, cudaStreamNonBlocking);
    return t;
}
static cudaEvent_t make_event() {
    cudaEvent_t t;
    cudaEventCreateWithFlags(&t, cudaEventDisableTiming);
    return t;
}
static cudaStream_t stream2() { static cudaStream_t s = make_stream(); return s; }
static cudaStream_t stream3() { static cudaStream_t s = make_stream(); return s; }
static cudaEvent_t ev_fork() { static cudaEvent_t e = make_event(); return e; }
static cudaEvent_t ev_hh()   { static cudaEvent_t e = make_event(); return e; }
static cudaEvent_t ev_cs()   { static cudaEvent_t e = make_event(); return e; }

extern "C" void kernel_launch(void* const* d_in, const int* in_sizes, int n_in,
                              void* d_out, int out_size) {
    const int*   tok    = (const int*)d_in[0];
    const float* hidden = (const float*)d_in[1];
    const float* enc    = (const float*)d_in[2];
    const float* emb    = (const float*)d_in[3];
    const float* comb_w = (const float*)d_in[6];
    const float* comb_b = (const float*)d_in[7];
    const float* w_ih   = (const float*)d_in[8];
    const float* w_hh   = (const float*)d_in[9];
    const float* b_ih   = (const float*)d_in[10];
    const float* b_hh   = (const float*)d_in[11];
    const float* out_w  = (const float*)d_in[12];
    const float* out_b  = (const float*)d_in[13];

    float* out      = (float*)d_out;
    float* out_h    = out + V;
    float* out_attn = out + V + H;

    cudaStream_t s2 = stream2(), s3 = stream3();
    cudaEvent_t eF = ev_fork(), eHH = ev_hh(), eCS = ev_cs();

    // fork both side streams from main
    cudaEventRecord(eF, 0);
    cudaStreamWaitEvent(s2, eF, 0);
    cudaStreamWaitEvent(s3, eF, 0);

    // s2: hh-gates (depends only on h0)
    gates_hh<<<384, 512, 0, s2>>>(w_hh, b_hh, hidden);
    cudaEventRecord(eHH, s2);

    // s3: attention colsum chain (independent of comb_emb)
    colsum_partial<<<dim3(8, 32), 256, 0, s3>>>(enc);
    colsum_reduce<<<32, 64, 0, s3>>>(out_attn);
    cudaEventRecord(eCS, s3);

    // main: embedded-half of comb runs concurrently with colsum + hh
    comb_emb<<<256, 256>>>(comb_w, emb, tok);
    cudaStreamWaitEvent(0, eCS, 0);         // need g_attn_applied
    comb_attn<<<256, 256>>>(comb_w);
    gates_ih<<<384, 512>>>(w_ih, b_ih, comb_b);
    cudaStreamWaitEvent(0, eHH, 0);         // need g_gh

    gru_combine<<<32, 64>>>(hidden, out_h);
    out_gemv<<<(V + 15) / 16, 512>>>(out_w, out_b);
    sumexp_partial<<<NPART, 256>>>();
    write_logprobs<<<(V + 255) / 256, 256>>>(out);
}

// round 16
// speedup vs baseline: 1.0228x; 1.0228x over previous
#include <cuda_runtime.h>

#define H 2048
#define S 2048
#define V 50257
#define CHUNKS 32
#define NPART 64

// ---- scratch ----
__device__ float g_attn_partial[CHUNKS * H];
__device__ float g_attn_applied[H];
__device__ float g_p1[H];         // comb partial: embedded half
__device__ float g_p2[H];         // comb partial: attn half
__device__ float g_gx[3 * H];
__device__ float g_gh[3 * H];
__device__ float g_hnew[H];
__device__ float g_logits[V];
__device__ float g_sumpart[NPART];

__device__ __forceinline__ float warp_sum(float v) {
#pragma unroll
    for (int o = 16; o > 0; o >>= 1) v += __shfl_down_sync(0xffffffffu, v, o);
    return v;
}

// ---- A: partial column sums of encoder_outputs (attn_weights are all 1.0) ----
__global__ void colsum_partial(const float* __restrict__ enc) {
    int col = blockIdx.x * 256 + threadIdx.x;          // 8 col-blocks
    int s0 = blockIdx.y * (S / CHUNKS);                // 32 row-chunks of 64
    float acc = 0.f;
#pragma unroll 8
    for (int s = 0; s < S / CHUNKS; ++s)
        acc += __ldg(&enc[(size_t)(s0 + s) * H + col]);
    g_attn_partial[blockIdx.y * H + col] = acc;
}

// ---- R: reduce partials -> attn_applied (32x64: spread latency-bound loads) ----
__global__ void colsum_reduce(float* __restrict__ out_attn) {
    int h = blockIdx.x * 64 + threadIdx.x;             // 32 blocks x 64 threads
    float acc = 0.f;
#pragma unroll
    for (int c = 0; c < CHUNKS; ++c) acc += g_attn_partial[c * H + h];
    g_attn_applied[h] = acc;
    out_attn[h] = 1.0f;   // out_attn only 4B-aligned: scalar store required
}

// ---- B: comb GEMV, K-split into half-rows (R14 exact). 512 blocks x 8 warps ----
__global__ void comb_part(const float* __restrict__ comb_w,
                          const float* __restrict__ emb,
                          const int* __restrict__ tok) {
    int warp = threadIdx.x >> 5, lane = threadIdx.x & 31;
    bool embhalf = (blockIdx.x < 256);
    int h = (embhalf ? blockIdx.x : blockIdx.x - 256) * 8 + warp;   // 0..2047
    const float4* w4 = (const float4*)(comb_w + (size_t)h * (2 * H) + (embhalf ? 0 : H));
    const float4* v4 = embhalf ? (const float4*)(emb + (size_t)tok[0] * H)
                               : (const float4*)g_attn_applied;
    float acc = 0.f;
#pragma unroll
    for (int i = 0; i < 16; ++i) {
        float4 wv = __ldcs(&w4[i * 32 + lane]);
        float4 xv = __ldg(&v4[i * 32 + lane]);
        acc += wv.x * xv.x + wv.y * xv.y + wv.z * xv.z + wv.w * xv.w;
    }
    acc = warp_sum(acc);
    if (lane == 0) {
        if (embhalf) g_p1[h] = acc;
        else         g_p2[h] = acc;
    }
}

// ---- C1: hh-gate GEMV (stream 2). 384 blocks x 16 warps, 1 row/warp ----
__global__ void __launch_bounds__(512)
gates_hh(const float* __restrict__ w_hh, const float* __restrict__ b_hh,
         const float* __restrict__ h0) {
    __shared__ float4 vs[H / 4];
    int tid = threadIdx.x;
    const float4* src = (const float4*)h0;
    for (int i = tid; i < H / 4; i += 512) vs[i] = __ldg(&src[i]);
    __syncthreads();
    int warp = tid >> 5, lane = tid & 31;
    int r = blockIdx.x * 16 + warp;                    // 0..6143
    const float4* w4 = (const float4*)(w_hh + (size_t)r * H);
    float acc = 0.f;
#pragma unroll
    for (int i = 0; i < 16; ++i) {
        float4 wv = __ldcs(&w4[i * 32 + lane]);
        float4 xv = vs[i * 32 + lane];
        acc += wv.x * xv.x + wv.y * xv.y + wv.z * xv.z + wv.w * xv.w;
    }
    acc = warp_sum(acc);
    if (lane == 0) g_gh[r] = acc + b_hh[r];
}

// ---- C2: ih-gate GEMV, split in halves across both streams.
//      192 blocks x 16 warps each; row_base selects half. Staging prologue
//      fuses the comb combine: x = relu(p1 + p2 + comb_b). ----
__global__ void __launch_bounds__(512)
gates_ih_half(const float* __restrict__ w_ih, const float* __restrict__ b_ih,
              const float* __restrict__ comb_b, int row_base) {
    __shared__ float4 vs[H / 4];
    int tid = threadIdx.x;
    const float4* p1 = (const float4*)g_p1;
    const float4* p2 = (const float4*)g_p2;
    const float4* cb = (const float4*)comb_b;
    for (int i = tid; i < H / 4; i += 512) {
        float4 a = p1[i], b = p2[i], c = __ldg(&cb[i]);
        float4 x;
        x.x = fmaxf(a.x + b.x + c.x, 0.f);
        x.y = fmaxf(a.y + b.y + c.y, 0.f);
        x.z = fmaxf(a.z + b.z + c.z, 0.f);
        x.w = fmaxf(a.w + b.w + c.w, 0.f);
        vs[i] = x;
    }
    __syncthreads();
    int warp = tid >> 5, lane = tid & 31;
    int r = row_base + blockIdx.x * 16 + warp;         // half of 0..6143
    const float4* w4 = (const float4*)(w_ih + (size_t)r * H);
    float acc = 0.f;
#pragma unroll
    for (int i = 0; i < 16; ++i) {
        float4 wv = __ldcs(&w4[i * 32 + lane]);
        float4 xv = vs[i * 32 + lane];
        acc += wv.x * xv.x + wv.y * xv.y + wv.z * xv.z + wv.w * xv.w;
    }
    acc = warp_sum(acc);
    if (lane == 0) g_gx[r] = acc + b_ih[r];
}

// ---- D: GRU nonlinearity -> h_new. 32 blocks x 64 threads ----
__global__ void gru_combine(const float* __restrict__ h0, float* __restrict__ out_h) {
    int h = blockIdx.x * 64 + threadIdx.x;
    float r = 1.f / (1.f + expf(-(g_gx[h] + g_gh[h])));
    float z = 1.f / (1.f + expf(-(g_gx[H + h] + g_gh[H + h])));
    float n = tanhf(g_gx[2 * H + h] + r * g_gh[2 * H + h]);
    float hn = (1.f - z) * n + z * h0[h];
    g_hnew[h] = hn;
    out_h[h] = hn;   // scalar store: out + V not 16B-aligned
}

// ---- E: big GEMV — 512-thread blocks (16 warps, 1 row/warp), no epilogue ----
__global__ void __launch_bounds__(512)
out_gemv(const float* __restrict__ out_w, const float* __restrict__ out_b) {
    __shared__ float4 hs[H / 4];
    for (int i = threadIdx.x; i < H / 4; i += 512)
        hs[i] = ((const float4*)g_hnew)[i];
    __syncthreads();
    int warp = threadIdx.x >> 5, lane = threadIdx.x & 31;
    int v = blockIdx.x * 16 + warp;
    if (v >= V) return;
    const float4* w4 = (const float4*)(out_w + (size_t)v * H);
    float acc = 0.f;
#pragma unroll
    for (int i = 0; i < 16; ++i) {
        float4 wv = __ldcs(&w4[i * 32 + lane]);
        float4 xv = hs[i * 32 + lane];
        acc += wv.x * xv.x + wv.y * xv.y + wv.z * xv.z + wv.w * xv.w;
    }
    acc = warp_sum(acc);
    if (lane == 0) g_logits[v] = acc + out_b[v];
}

// ---- F1: partial sum of exp(logits). Logits are O(1): exp safe without max ----
__global__ void sumexp_partial() {
    __shared__ float red[8];
    int t = threadIdx.x;
    float s = 0.f;
    for (int i = blockIdx.x * 256 + t; i < V; i += NPART * 256)
        s += __expf(g_logits[i]);
    s = warp_sum(s);
    if ((t & 31) == 0) red[t >> 5] = s;
    __syncthreads();
    if (t == 0) {
        float ss = 0.f;
#pragma unroll
        for (int j = 0; j < 8; ++j) ss += red[j];
        g_sumpart[blockIdx.x] = ss;
    }
}

// ---- F2: fold partials (deterministic fixed order) and write log_probs ----
__global__ void write_logprobs(float* __restrict__ out) {
    float s = 0.f;
#pragma unroll
    for (int j = 0; j < NPART; ++j) s += g_sumpart[j];
    float lse = logf(s);
    int v = blockIdx.x * 256 + threadIdx.x;
    if (v < V) out[v] = g_logits[v] - lse;
}

// ---- infra: side stream + events (created once; no device memory) ----
static cudaStream_t make_stream() {
    cudaStream_t t;
    cudaStreamCreateWithFlags(&t, cudaStreamNonBlocking);
    return t;
}
static cudaEvent_t make_event() {
    cudaEvent_t t;
    cudaEventCreateWithFlags(&t, cudaEventDisableTiming);
    return t;
}
static cudaStream_t stream2() { static cudaStream_t s = make_stream(); return s; }
static cudaEvent_t ev_fork() { static cudaEvent_t e = make_event(); return e; }
static cudaEvent_t ev_x()    { static cudaEvent_t e = make_event(); return e; }
static cudaEvent_t ev_join() { static cudaEvent_t e = make_event(); return e; }

extern "C" void kernel_launch(void* const* d_in, const int* in_sizes, int n_in,
                              void* d_out, int out_size) {
    const int*   tok    = (const int*)d_in[0];
    const float* hidden = (const float*)d_in[1];
    const float* enc    = (const float*)d_in[2];
    const float* emb    = (const float*)d_in[3];
    const float* comb_w = (const float*)d_in[6];
    const float* comb_b = (const float*)d_in[7];
    const float* w_ih   = (const float*)d_in[8];
    const float* w_hh   = (const float*)d_in[9];
    const float* b_ih   = (const float*)d_in[10];
    const float* b_hh   = (const float*)d_in[11];
    const float* out_w  = (const float*)d_in[12];
    const float* out_b  = (const float*)d_in[13];

    float* out      = (float*)d_out;
    float* out_h    = out + V;
    float* out_attn = out + V + H;

    cudaStream_t s2 = stream2();
    cudaEvent_t eF = ev_fork(), eX = ev_x(), eJ = ev_join();

    // fork: s2 runs hh-gates (depends only on h0)
    cudaEventRecord(eF, 0);
    cudaStreamWaitEvent(s2, eF, 0);
    gates_hh<<<384, 512, 0, s2>>>(w_hh, b_hh, hidden);

    // main: attention path -> comb halves (R14 unified kernel)
    colsum_partial<<<dim3(8, 32), 256>>>(enc);
    colsum_reduce<<<32, 64>>>(out_attn);
    comb_part<<<512, 256>>>(comb_w, emb, tok);
    cudaEventRecord(eX, 0);                 // g_p1/g_p2 ready

    // split ih across both streams: rows 0..3071 on main, 3072..6143 on s2
    cudaStreamWaitEvent(s2, eX, 0);
    gates_ih_half<<<192, 512, 0, s2>>>(w_ih, b_ih, comb_b, 3072);
    cudaEventRecord(eJ, s2);
    gates_ih_half<<<192, 512>>>(w_ih, b_ih, comb_b, 0);
    cudaStreamWaitEvent(0, eJ, 0);          // need g_gh + upper g_gx

    gru_combine<<<32, 64>>>(hidden, out_h);
    out_gemv<<<(V + 15) / 16, 512>>>(out_w, out_b);
    sumexp_partial<<<NPART, 256>>>();
    write_logprobs<<<(V + 255) / 256, 256>>>(out);
}